// round 4
// baseline (speedup 1.0000x reference)
#include <cuda_runtime.h>
#include <cstdint>

#define HID 128
#define NB 50000
#define NC 2500
#define NLAYERS 2
#define NBF (NB*HID)
#define NCF (NC*HID)

#define BSTR 136                      // bf16 elements per smem row (128 + 8 pad)
#define ATILE (64*BSTR*2)             // 17408 B (64-row bf16 tile)
#define BTILE (128*BSTR*2)            // 34816 B (128-row bf16 tile)
#define SOFF_AH 0
#define SOFF_AL (ATILE)
#define SOFF_BH (2*ATILE)
#define SOFF_BL (2*ATILE + BTILE)
#define SMEM_TOTAL (2*ATILE + 2*BTILE)  // 104448 B -> 2 CTAs/SM
#define CSTR 132                      // f32 epilogue tile stride

// ---------------- helpers ----------------
__device__ __forceinline__ uint32_t smem_u32(const void* p){
    uint32_t a; asm("{ .reg .u64 t; cvta.to.shared.u64 t, %1; cvt.u32.u64 %0, t; }" : "=r"(a) : "l"(p));
    return a;
}
__device__ __forceinline__ float gelu_f(float x){
    return 0.5f * x * (1.0f + erff(x * 0.70710678118654752440f));
}
__device__ __forceinline__ void red_add_v4(float* p, float a, float b, float c, float d){
    asm volatile("red.global.add.v4.f32 [%0], {%1, %2, %3, %4};"
                 :: "l"(p), "f"(a), "f"(b), "f"(c), "f"(d) : "memory");
}
// split (x,y) into packed bf16x2 hi (truncation) and lo (round-to-nearest of residual)
__device__ __forceinline__ void split2(float x, float y, uint32_t& hi, uint32_t& lo){
    uint32_t ux = __float_as_uint(x), uy = __float_as_uint(y);
    hi = (ux >> 16) | (uy & 0xFFFF0000u);
    float lx = x - __uint_as_float(ux & 0xFFFF0000u);
    float ly = y - __uint_as_float(uy & 0xFFFF0000u);
    asm("cvt.rn.bf16x2.f32 %0, %1, %2;" : "=r"(lo) : "f"(ly), "f"(lx));
}
__device__ __forceinline__ void ldsm_x4(uint32_t* r, uint32_t addr){
    asm volatile("ldmatrix.sync.aligned.m8n8.x4.shared.b16 {%0,%1,%2,%3}, [%4];"
        : "=r"(r[0]), "=r"(r[1]), "=r"(r[2]), "=r"(r[3]) : "r"(addr));
}
__device__ __forceinline__ void ldsm_x4t(uint32_t* r, uint32_t addr){
    asm volatile("ldmatrix.sync.aligned.m8n8.x4.trans.shared.b16 {%0,%1,%2,%3}, [%4];"
        : "=r"(r[0]), "=r"(r[1]), "=r"(r[2]), "=r"(r[3]) : "r"(addr));
}
__device__ __forceinline__ void mma16816(float* c, const uint32_t* a, uint32_t b0, uint32_t b1){
    asm volatile("mma.sync.aligned.m16n8k16.row.col.f32.bf16.bf16.f32 "
        "{%0,%1,%2,%3}, {%4,%5,%6,%7}, {%8,%9}, {%0,%1,%2,%3};"
        : "+f"(c[0]), "+f"(c[1]), "+f"(c[2]), "+f"(c[3])
        : "r"(a[0]), "r"(a[1]), "r"(a[2]), "r"(a[3]), "r"(b0), "r"(b1));
}

// ------------- fused tile kernel: D = (scale*A) @ W, 3xBF16 split on HMMA -------------
// 64-row tiles, 8 warps (4m x 2n), 2 CTAs/SM.
// edge mode (ei!=null): m = gelu(D + bias + XS[src]) * ew -> red.add into OUT[dst]
// linear mode:          OUT[row] = [gelu]( D + bias )
extern "C" __global__ void __launch_bounds__(256, 2)
tile_gemm(const float* __restrict__ A, const float* __restrict__ W,
          const float* __restrict__ bias, const int* __restrict__ ei,
          const float* __restrict__ ew, const float* __restrict__ XS,
          float* __restrict__ OUT, int M, const float* __restrict__ eps_ptr,
          int do_gelu)
{
    extern __shared__ char smem[];
    uint32_t* sm32 = (uint32_t*)smem;
    int t = threadIdx.x;
    int w = t >> 5, l = t & 31;
    const bool edge = (ei != nullptr);
    float scale = eps_ptr ? (1.0f + *eps_ptr) : 1.0f;
    int row0 = blockIdx.x * 64;

    // ---- stage A rows (fp32 -> bf16 hi/lo, scale folded): 4 threads/row ----
    {
        int r = t >> 2, q = t & 3;
        int grow = row0 + r;
        bool v = (grow < M);
        const float4* g = (const float4*)(A + (size_t)grow * HID) + q * 8;
        uint32_t* ah = sm32 + (SOFF_AH >> 2) + r * (BSTR >> 1) + q * 16;
        uint32_t* al = sm32 + (SOFF_AL >> 2) + r * (BSTR >> 1) + q * 16;
        #pragma unroll
        for (int i = 0; i < 8; i++){
            float4 x = v ? g[i] : make_float4(0.f, 0.f, 0.f, 0.f);
            x.x *= scale; x.y *= scale; x.z *= scale; x.w *= scale;
            uint32_t h0, l0, h1, l1;
            split2(x.x, x.y, h0, l0); split2(x.z, x.w, h1, l1);
            ah[2*i] = h0; ah[2*i+1] = h1;
            al[2*i] = l0; al[2*i+1] = l1;
        }
    }
    // ---- stage W rows [k][n] (ldmatrix.trans provides col-major B frags) ----
    {
        int k = t >> 1, half = t & 1;
        const float4* g = (const float4*)(W + (size_t)k * HID) + half * 16;
        uint32_t* bh = sm32 + (SOFF_BH >> 2) + k * (BSTR >> 1) + half * 32;
        uint32_t* bl = sm32 + (SOFF_BL >> 2) + k * (BSTR >> 1) + half * 32;
        #pragma unroll
        for (int i = 0; i < 16; i++){
            float4 x = g[i];
            uint32_t h0, l0, h1, l1;
            split2(x.x, x.y, h0, l0); split2(x.z, x.w, h1, l1);
            bh[2*i] = h0; bh[2*i+1] = h1;
            bl[2*i] = l0; bl[2*i+1] = l1;
        }
    }
    __syncthreads();

    // ---- HMMA mainloop: warp (wm,wn) owns rows 16wm..+15, cols 64wn..+63 ----
    int wm = w & 3, wn = w >> 2;
    float acc[8][4];
    #pragma unroll
    for (int n = 0; n < 8; n++){
        acc[n][0] = 0.f; acc[n][1] = 0.f; acc[n][2] = 0.f; acc[n][3] = 0.f;
    }
    uint32_t sbase = smem_u32(smem);
    int arow = 16 * wm + (l & 15);
    int akoff = (l >> 4) * 8;
    uint32_t aAh = sbase + SOFF_AH + (uint32_t)(arow * BSTR + akoff) * 2;
    uint32_t aAl = sbase + SOFF_AL + (uint32_t)(arow * BSTR + akoff) * 2;
    // B x4.trans: lanes 0-15 -> n-tile 2p (k rows 0..15), lanes 16-31 -> n-tile 2p+1
    uint32_t bcol = (uint32_t)(128 * wn + 16 * (l >> 4));
    uint32_t aBh = sbase + SOFF_BH + (uint32_t)((l & 15) * BSTR) * 2 + bcol;
    uint32_t aBl = sbase + SOFF_BL + (uint32_t)((l & 15) * BSTR) * 2 + bcol;

    #pragma unroll 1
    for (int ks = 0; ks < 8; ks++){
        uint32_t ah[4], al[4];
        ldsm_x4(ah, aAh);
        ldsm_x4(al, aAl);
        aAh += 32; aAl += 32;           // k += 16 (bytes)
        #pragma unroll
        for (int p = 0; p < 4; p++){
            uint32_t bh[4], bl[4];
            ldsm_x4t(bh, aBh + 32 * p);
            ldsm_x4t(bl, aBl + 32 * p);
            mma16816(acc[2*p],   ah, bh[0], bh[1]);
            mma16816(acc[2*p],   ah, bl[0], bl[1]);
            mma16816(acc[2*p],   al, bh[0], bh[1]);
            mma16816(acc[2*p+1], ah, bh[2], bh[3]);
            mma16816(acc[2*p+1], ah, bl[2], bl[3]);
            mma16816(acc[2*p+1], al, bh[2], bh[3]);
        }
        aBh += 16 * BSTR * 2;           // next 16 k-rows
        aBl += 16 * BSTR * 2;
    }

    // ---- accumulators -> smem f32 tile (reuse A region: 64*CSTR*4 = 33792 <= 2*ATILE) ----
    __syncthreads();
    float* Cs = (float*)smem;
    {
        int r0 = 16 * wm + (l >> 2);
        int cb = 64 * wn + 2 * (l & 3);
        #pragma unroll
        for (int n = 0; n < 8; n++){
            int c = cb + 8 * n;
            *(float2*)(Cs + r0 * CSTR + c)       = make_float2(acc[n][0], acc[n][1]);
            *(float2*)(Cs + (r0 + 8) * CSTR + c) = make_float2(acc[n][2], acc[n][3]);
        }
    }
    __syncthreads();

    // ---- fused epilogue: 4 threads per row ----
    {
        int r = t >> 2, q = t & 3;
        int grow = row0 + r;
        if (grow < M){
            int c0 = q * 32;
            if (!edge){
                float4* o4 = (float4*)(OUT + (size_t)grow * HID + c0);
                #pragma unroll
                for (int i = 0; i < 8; i++){
                    int c = c0 + 4 * i;
                    float4 bv = *(const float4*)(bias + c);
                    float o0 = Cs[r * CSTR + c + 0] + bv.x;
                    float o1 = Cs[r * CSTR + c + 1] + bv.y;
                    float o2 = Cs[r * CSTR + c + 2] + bv.z;
                    float o3 = Cs[r * CSTR + c + 3] + bv.w;
                    if (do_gelu){ o0 = gelu_f(o0); o1 = gelu_f(o1); o2 = gelu_f(o2); o3 = gelu_f(o3); }
                    o4[i] = make_float4(o0, o1, o2, o3);
                }
            } else {
                int src = ei[grow], dst = ei[M + grow];
                float wgt = ew[grow];
                const float4* xs4 = (const float4*)(XS + (size_t)src * HID);
                #pragma unroll
                for (int i = 0; i < 8; i++){
                    int c = c0 + 4 * i;
                    float4 bv = *(const float4*)(bias + c);
                    float4 xv = xs4[c >> 2];
                    float m0 = gelu_f(Cs[r * CSTR + c + 0] + bv.x + xv.x) * wgt;
                    float m1 = gelu_f(Cs[r * CSTR + c + 1] + bv.y + xv.y) * wgt;
                    float m2 = gelu_f(Cs[r * CSTR + c + 2] + bv.z + xv.z) * wgt;
                    float m3 = gelu_f(Cs[r * CSTR + c + 3] + bv.w + xv.w) * wgt;
                    red_add_v4(OUT + (size_t)dst * HID + c, m0, m1, m2, m3);
                }
            }
        }
    }
}

// ---------- x += gelu(a + b) ----------
extern "C" __global__ void combine_kernel(float* __restrict__ x, const float* __restrict__ a,
                                          const float* __restrict__ b, int n){
    int i = blockIdx.x * blockDim.x + threadIdx.x;
    if (i < n) x[i] += gelu_f(a[i] + b[i]);
}

// ---------- scratch ----------
__device__ float g_buf[(size_t)5*NBF + (size_t)5*NCF];

extern "C" void kernel_launch(void* const* d_in, const int* in_sizes, int n_in,
                              void* d_out, int out_size)
{
    (void)n_in; (void)out_size;
    const float* x_base = (const float*)d_in[0];
    const float* x_cent = (const float*)d_in[1];
    const int*   ei[4]  = {(const int*)d_in[2], (const int*)d_in[5], (const int*)d_in[8],  (const int*)d_in[11]};
    const float* ea[4]  = {(const float*)d_in[3], (const float*)d_in[6], (const float*)d_in[9],  (const float*)d_in[12]};
    const float* ewt[4] = {(const float*)d_in[4], (const float*)d_in[7], (const float*)d_in[10], (const float*)d_in[13]};
    const float* Wsrc = (const float*)d_in[14];
    const float* bsrc = (const float*)d_in[15];
    const float* Wdst = (const float*)d_in[16];
    const float* bdst = (const float*)d_in[17];
    const float* eps  = (const float*)d_in[18];
    const float* We   = (const float*)d_in[19];
    const float* be   = (const float*)d_in[20];
    const float* Wm1  = (const float*)d_in[21];
    const float* bm1  = (const float*)d_in[22];
    const float* Wm2  = (const float*)d_in[23];
    const float* bm2  = (const float*)d_in[24];

    float* base = nullptr;
    cudaGetSymbolAddress((void**)&base, g_buf);
    float* xb     = base;
    float* xs_bb  = base + (size_t)1*NBF;
    float* xs_bc  = base + (size_t)2*NBF;
    float* agg_bb = base + (size_t)3*NBF;
    float* agg_cb = base + (size_t)4*NBF;
    float* xc     = base + (size_t)5*NBF;
    float* xs_cc  = xc + (size_t)1*NCF;
    float* xs_cb  = xc + (size_t)2*NCF;
    float* agg_bc = xc + (size_t)3*NCF;
    float* agg_cc = xc + (size_t)4*NCF;

    cudaFuncSetAttribute((const void*)tile_gemm, cudaFuncAttributeMaxDynamicSharedMemorySize, SMEM_TOTAL);

    cudaMemcpyAsync(xb, x_base, sizeof(float)*(size_t)NBF, cudaMemcpyDeviceToDevice, 0);
    cudaMemcpyAsync(xc, x_cent, sizeof(float)*(size_t)NCF, cudaMemcpyDeviceToDevice, 0);

    const int GB = (NB + 63) / 64;
    const int GC = (NC + 63) / 64;

    for (int l = 0; l < NLAYERS; l++){
        #define WOFF(P,t) ((P) + ((size_t)l*4 + (t))*HID*HID)
        #define BOFF(P,t) ((P) + ((size_t)l*4 + (t))*HID)
        // lin_src per edge type: xs = x_src @ Wsrc + bsrc
        tile_gemm<<<GB, 256, SMEM_TOTAL>>>(xb, WOFF(Wsrc,0), BOFF(bsrc,0), nullptr, nullptr, nullptr, xs_bb, NB, nullptr, 0);
        tile_gemm<<<GB, 256, SMEM_TOTAL>>>(xb, WOFF(Wsrc,1), BOFF(bsrc,1), nullptr, nullptr, nullptr, xs_bc, NB, nullptr, 0);
        tile_gemm<<<GC, 256, SMEM_TOTAL>>>(xc, WOFF(Wsrc,2), BOFF(bsrc,2), nullptr, nullptr, nullptr, xs_cc, NC, nullptr, 0);
        tile_gemm<<<GC, 256, SMEM_TOTAL>>>(xc, WOFF(Wsrc,3), BOFF(bsrc,3), nullptr, nullptr, nullptr, xs_cb, NC, nullptr, 0);
        // agg init: ((1+eps)*x_dst) @ Wdst + bdst
        tile_gemm<<<GB, 256, SMEM_TOTAL>>>(xb, WOFF(Wdst,0), BOFF(bdst,0), nullptr, nullptr, nullptr, agg_bb, NB, eps + l*4 + 0, 0);
        tile_gemm<<<GB, 256, SMEM_TOTAL>>>(xb, WOFF(Wdst,3), BOFF(bdst,3), nullptr, nullptr, nullptr, agg_cb, NB, eps + l*4 + 3, 0);
        tile_gemm<<<GC, 256, SMEM_TOTAL>>>(xc, WOFF(Wdst,1), BOFF(bdst,1), nullptr, nullptr, nullptr, agg_bc, NC, eps + l*4 + 1, 0);
        tile_gemm<<<GC, 256, SMEM_TOTAL>>>(xc, WOFF(Wdst,2), BOFF(bdst,2), nullptr, nullptr, nullptr, agg_cc, NC, eps + l*4 + 2, 0);
        // fused edge encode + message + scatter
        {
            const float* XSs[4]  = {xs_bb, xs_bc, xs_cc, xs_cb};
            float*       AGGs[4] = {agg_bb, agg_bc, agg_cc, agg_cb};
            for (int tt = 0; tt < 4; tt++){
                int E = in_sizes[4 + 3*tt];
                tile_gemm<<<(E + 63)/64, 256, SMEM_TOTAL>>>(ea[tt], WOFF(We,tt), BOFF(be,tt),
                                                            ei[tt], ewt[tt], XSs[tt], AGGs[tt], E, nullptr, 0);
            }
        }
        // MLP layer 1 (gelu)
        tile_gemm<<<GB, 256, SMEM_TOTAL>>>(agg_bb, WOFF(Wm1,0), BOFF(bm1,0), nullptr, nullptr, nullptr, xs_bb, NB, nullptr, 1);
        tile_gemm<<<GB, 256, SMEM_TOTAL>>>(agg_cb, WOFF(Wm1,3), BOFF(bm1,3), nullptr, nullptr, nullptr, xs_bc, NB, nullptr, 1);
        tile_gemm<<<GC, 256, SMEM_TOTAL>>>(agg_bc, WOFF(Wm1,1), BOFF(bm1,1), nullptr, nullptr, nullptr, xs_cc, NC, nullptr, 1);
        tile_gemm<<<GC, 256, SMEM_TOTAL>>>(agg_cc, WOFF(Wm1,2), BOFF(bm1,2), nullptr, nullptr, nullptr, xs_cb, NC, nullptr, 1);
        // MLP layer 2
        tile_gemm<<<GB, 256, SMEM_TOTAL>>>(xs_bb, WOFF(Wm2,0), BOFF(bm2,0), nullptr, nullptr, nullptr, agg_bb, NB, nullptr, 0);
        tile_gemm<<<GB, 256, SMEM_TOTAL>>>(xs_bc, WOFF(Wm2,3), BOFF(bm2,3), nullptr, nullptr, nullptr, agg_cb, NB, nullptr, 0);
        tile_gemm<<<GC, 256, SMEM_TOTAL>>>(xs_cc, WOFF(Wm2,1), BOFF(bm2,1), nullptr, nullptr, nullptr, agg_bc, NC, nullptr, 0);
        tile_gemm<<<GC, 256, SMEM_TOTAL>>>(xs_cb, WOFF(Wm2,2), BOFF(bm2,2), nullptr, nullptr, nullptr, agg_cc, NC, nullptr, 0);
        // residual + gelu combine
        combine_kernel<<<(NBF+255)/256, 256>>>(xb, agg_bb, agg_cb, NBF);
        combine_kernel<<<(NCF+255)/256, 256>>>(xc, agg_bc, agg_cc, NCF);
        #undef WOFF
        #undef BOFF
    }

    float* out = (float*)d_out;
    cudaMemcpyAsync(out,       xb, sizeof(float)*(size_t)NBF, cudaMemcpyDeviceToDevice, 0);
    cudaMemcpyAsync(out + NBF, xc, sizeof(float)*(size_t)NCF, cudaMemcpyDeviceToDevice, 0);
}

// round 5
// speedup vs baseline: 1.3093x; 1.3093x over previous
#include <cuda_runtime.h>
#include <cstdint>

#define HID 128
#define NB 50000
#define NC 2500
#define NLAYERS 2
#define NBF (NB*HID)
#define NCF (NC*HID)

typedef unsigned long long u64;

#define SA_STRIDE 132
#define SMEM_BYTES ((HID*HID + 64*SA_STRIDE)*4)   // 99328 B -> 2 CTAs/SM
#define GRID_P 296                                 // 2 per SM persistent

#define FLAG_GELU 1
#define FLAG_EDGE 2

// ---------- packed f32x2 helpers ----------
__device__ __forceinline__ u64 pack2(float x, float y){
    u64 d; asm("mov.b64 %0, {%1, %2};" : "=l"(d) : "f"(x), "f"(y)); return d;
}
__device__ __forceinline__ float2 unpack2(u64 d){
    float2 v; asm("mov.b64 {%0, %1}, %2;" : "=f"(v.x), "=f"(v.y) : "l"(d)); return v;
}
__device__ __forceinline__ u64 fma2(u64 a, u64 b, u64 c){
    u64 d; asm("fma.rn.f32x2 %0, %1, %2, %3;" : "=l"(d) : "l"(a), "l"(b), "l"(c)); return d;
}
__device__ __forceinline__ float gelu_f(float x){
    return 0.5f * x * (1.0f + erff(x * 0.70710678118654752440f));
}
__device__ __forceinline__ void red_add_v4(float* p, float a, float b, float c, float d){
    asm volatile("red.global.add.v4.f32 [%0], {%1, %2, %3, %4};"
                 :: "l"(p), "f"(a), "f"(b), "f"(c), "f"(d) : "memory");
}

// ---------- job table (passed by value; snapshotted by graph capture) ----------
struct Job {
    const float* A; const float* W; const float* bias;
    float* out;
    const int* ei; const float* ew; const float* xs;
    const float* eps;           // nullable: scale = 1 + *eps
    int rows; int tile_ofs; int flags; int _pad;
};
struct JobTab { Job j[8]; int njobs; int total_tiles; };

// ---------- GEMM mainloop: C(64x128), K=128, FFMA2 ----------
// thread t: tr=t/16 rows 4tr..+3 ; tc=t%15 cols {4tc..+3, 4tc+64..+67}
__device__ __forceinline__ void gemm_mainloop(const float* sW, const float* sA,
                                              int r0, int tc, u64 acc[4][2][2]){
    #pragma unroll
    for (int r=0;r<4;r++)
        #pragma unroll
        for (int j=0;j<2;j++){ acc[r][j][0]=0ULL; acc[r][j][1]=0ULL; }
    #pragma unroll 2
    for (int k0 = 0; k0 < HID; k0 += 4){
        float4 av[4];
        #pragma unroll
        for (int r=0;r<4;r++)
            av[r] = *reinterpret_cast<const float4*>(sA + (r0+r)*SA_STRIDE + k0);
        #pragma unroll
        for (int kk=0;kk<4;kk++){
            const float* wrow = sW + (k0+kk)*HID + 4*tc;
            ulonglong2 w0 = *reinterpret_cast<const ulonglong2*>(wrow);
            ulonglong2 w1 = *reinterpret_cast<const ulonglong2*>(wrow + 64);
            #pragma unroll
            for (int r=0;r<4;r++){
                float a = (kk==0)?av[r].x:(kk==1)?av[r].y:(kk==2)?av[r].z:av[r].w;
                u64 a2 = pack2(a, a);
                acc[r][0][0] = fma2(a2, w0.x, acc[r][0][0]);
                acc[r][0][1] = fma2(a2, w0.y, acc[r][0][1]);
                acc[r][1][0] = fma2(a2, w1.x, acc[r][1][0]);
                acc[r][1][1] = fma2(a2, w1.y, acc[r][1][1]);
            }
        }
    }
}

// ---------- persistent multi-job fused GEMM kernel ----------
extern "C" __global__ void __launch_bounds__(256, 2)
mega_gemm(JobTab tab)
{
    extern __shared__ float smem[];
    float* sW = smem;                 // 128*128 f32
    float* sA = smem + HID*HID;       // 64*132 f32
    int t = threadIdx.x;
    int tr = t >> 4, tc = t & 15, r0 = tr * 4;
    int cached = -1;
    float scale = 1.0f;

    for (int tile = blockIdx.x; tile < tab.total_tiles; tile += gridDim.x){
        int jid = 0;
        #pragma unroll
        for (int q = 1; q < 8; q++)
            if (q < tab.njobs && tile >= tab.j[q].tile_ofs) jid = q;
        const Job J = tab.j[jid];
        int row0 = (tile - J.tile_ofs) * 64;

        __syncthreads();   // previous iteration done reading sA/sW
        if (jid != cached){
            const float4* W4 = (const float4*)J.W;
            float4* s4 = (float4*)sW;
            #pragma unroll
            for (int i = 0; i < 16; i++) s4[t + 256*i] = W4[t + 256*i];
            cached = jid;
            scale = J.eps ? (1.0f + *J.eps) : 1.0f;
        }
        {
            const float4* A4 = (const float4*)J.A;
            #pragma unroll
            for (int i = 0; i < 8; i++){
                int idx = t + 256*i;
                int r = idx >> 5, c4 = idx & 31;
                float4 v = make_float4(0.f,0.f,0.f,0.f);
                if (row0 + r < J.rows) v = A4[(size_t)(row0 + r)*32 + c4];
                v.x *= scale; v.y *= scale; v.z *= scale; v.w *= scale;
                *reinterpret_cast<float4*>(sA + r*SA_STRIDE + 4*c4) = v;
            }
        }
        __syncthreads();

        u64 acc[4][2][2];
        gemm_mainloop(sW, sA, r0, tc, acc);

        if (!(J.flags & FLAG_EDGE)){
            #pragma unroll
            for (int r=0;r<4;r++){
                int row = row0 + r0 + r;
                if (row >= J.rows) continue;
                #pragma unroll
                for (int j=0;j<2;j++){
                    int c = 4*tc + 64*j;
                    float4 bv = *reinterpret_cast<const float4*>(J.bias + c);
                    float2 v0 = unpack2(acc[r][j][0]);
                    float2 v1 = unpack2(acc[r][j][1]);
                    float o0 = v0.x + bv.x, o1 = v0.y + bv.y;
                    float o2 = v1.x + bv.z, o3 = v1.y + bv.w;
                    if (J.flags & FLAG_GELU){ o0=gelu_f(o0); o1=gelu_f(o1); o2=gelu_f(o2); o3=gelu_f(o3); }
                    *reinterpret_cast<float4*>(J.out + (size_t)row*HID + c) = make_float4(o0,o1,o2,o3);
                }
            }
        } else {
            #pragma unroll
            for (int r=0;r<4;r++){
                int e = row0 + r0 + r;
                if (e >= J.rows) continue;
                int src = J.ei[e];
                int dst = J.ei[J.rows + e];
                float wgt = J.ew[e];
                #pragma unroll
                for (int j=0;j<2;j++){
                    int c = 4*tc + 64*j;
                    float4 bv = *reinterpret_cast<const float4*>(J.bias + c);
                    float4 xv = *reinterpret_cast<const float4*>(J.xs + (size_t)src*HID + c);
                    float2 v0 = unpack2(acc[r][j][0]);
                    float2 v1 = unpack2(acc[r][j][1]);
                    float m0 = gelu_f(v0.x + bv.x + xv.x) * wgt;
                    float m1 = gelu_f(v0.y + bv.y + xv.y) * wgt;
                    float m2 = gelu_f(v1.x + bv.z + xv.z) * wgt;
                    float m3 = gelu_f(v1.y + bv.w + xv.w) * wgt;
                    red_add_v4(J.out + (size_t)dst*HID + c, m0, m1, m2, m3);
                }
            }
        }
    }
}

// ---------- x += gelu(a + b) ----------
extern "C" __global__ void combine_kernel(float* __restrict__ x, const float* __restrict__ a,
                                          const float* __restrict__ b, int n){
    int i = blockIdx.x * blockDim.x + threadIdx.x;
    if (i < n) x[i] += gelu_f(a[i] + b[i]);
}

// ---------- scratch ----------
__device__ float g_buf[(size_t)5*NBF + (size_t)5*NCF];

static void addJob(JobTab& T, const float* A, const float* W, const float* b, float* out,
                   int rows, const float* eps, int flags,
                   const int* ei = nullptr, const float* ew = nullptr, const float* xs = nullptr){
    Job& J = T.j[T.njobs];
    J.A = A; J.W = W; J.bias = b; J.out = out;
    J.ei = ei; J.ew = ew; J.xs = xs; J.eps = eps;
    J.rows = rows; J.tile_ofs = T.total_tiles; J.flags = flags; J._pad = 0;
    T.total_tiles += (rows + 63) / 64;
    T.njobs++;
}
static void launch_tab(const JobTab& T){
    int G = T.total_tiles < GRID_P ? T.total_tiles : GRID_P;
    mega_gemm<<<G, 256, SMEM_BYTES>>>(T);
}

extern "C" void kernel_launch(void* const* d_in, const int* in_sizes, int n_in,
                              void* d_out, int out_size)
{
    (void)n_in; (void)out_size;
    const float* x_base = (const float*)d_in[0];
    const float* x_cent = (const float*)d_in[1];
    const int*   ei[4]  = {(const int*)d_in[2], (const int*)d_in[5], (const int*)d_in[8],  (const int*)d_in[11]};
    const float* ea[4]  = {(const float*)d_in[3], (const float*)d_in[6], (const float*)d_in[9],  (const float*)d_in[12]};
    const float* ewt[4] = {(const float*)d_in[4], (const float*)d_in[7], (const float*)d_in[10], (const float*)d_in[13]};
    const float* Wsrc = (const float*)d_in[14];
    const float* bsrc = (const float*)d_in[15];
    const float* Wdst = (const float*)d_in[16];
    const float* bdst = (const float*)d_in[17];
    const float* eps  = (const float*)d_in[18];
    const float* We   = (const float*)d_in[19];
    const float* be   = (const float*)d_in[20];
    const float* Wm1  = (const float*)d_in[21];
    const float* bm1  = (const float*)d_in[22];
    const float* Wm2  = (const float*)d_in[23];
    const float* bm2  = (const float*)d_in[24];

    float* base = nullptr;
    cudaGetSymbolAddress((void**)&base, g_buf);
    float* xb     = base;
    float* xs_bb  = base + (size_t)1*NBF;
    float* xs_bc  = base + (size_t)2*NBF;
    float* agg_bb = base + (size_t)3*NBF;
    float* agg_cb = base + (size_t)4*NBF;
    float* xc     = base + (size_t)5*NBF;
    float* xs_cc  = xc + (size_t)1*NCF;
    float* xs_cb  = xc + (size_t)2*NCF;
    float* agg_bc = xc + (size_t)3*NCF;
    float* agg_cc = xc + (size_t)4*NCF;

    cudaFuncSetAttribute((const void*)mega_gemm, cudaFuncAttributeMaxDynamicSharedMemorySize, SMEM_BYTES);

    cudaMemcpyAsync(xb, x_base, sizeof(float)*(size_t)NBF, cudaMemcpyDeviceToDevice, 0);
    cudaMemcpyAsync(xc, x_cent, sizeof(float)*(size_t)NCF, cudaMemcpyDeviceToDevice, 0);

    for (int l = 0; l < NLAYERS; l++){
        #define WOFF(P,t) ((P) + ((size_t)l*4 + (t))*HID*HID)
        #define BOFF(P,t) ((P) + ((size_t)l*4 + (t))*HID)

        // --- NODE8: 4x lin_src + 4x lin_dst (agg init) in one launch ---
        {
            JobTab T = {};
            addJob(T, xb, WOFF(Wsrc,0), BOFF(bsrc,0), xs_bb, NB, nullptr, 0);
            addJob(T, xb, WOFF(Wsrc,1), BOFF(bsrc,1), xs_bc, NB, nullptr, 0);
            addJob(T, xc, WOFF(Wsrc,2), BOFF(bsrc,2), xs_cc, NC, nullptr, 0);
            addJob(T, xc, WOFF(Wsrc,3), BOFF(bsrc,3), xs_cb, NC, nullptr, 0);
            addJob(T, xb, WOFF(Wdst,0), BOFF(bdst,0), agg_bb, NB, eps + l*4 + 0, 0);
            addJob(T, xb, WOFF(Wdst,3), BOFF(bdst,3), agg_cb, NB, eps + l*4 + 3, 0);
            addJob(T, xc, WOFF(Wdst,1), BOFF(bdst,1), agg_bc, NC, eps + l*4 + 1, 0);
            addJob(T, xc, WOFF(Wdst,2), BOFF(bdst,2), agg_cc, NC, eps + l*4 + 2, 0);
            launch_tab(T);
        }
        // --- EDGE4: all 4 edge types in one launch ---
        {
            const float* XSs[4]  = {xs_bb, xs_bc, xs_cc, xs_cb};
            float*       AGGs[4] = {agg_bb, agg_bc, agg_cc, agg_cb};
            JobTab T = {};
            for (int tt = 0; tt < 4; tt++){
                int E = in_sizes[4 + 3*tt];
                addJob(T, ea[tt], WOFF(We,tt), BOFF(be,tt), AGGs[tt], E, nullptr, FLAG_EDGE,
                       ei[tt], ewt[tt], XSs[tt]);
            }
            launch_tab(T);
        }
        // --- MLP1 (gelu) ---
        {
            JobTab T = {};
            addJob(T, agg_bb, WOFF(Wm1,0), BOFF(bm1,0), xs_bb, NB, nullptr, FLAG_GELU);
            addJob(T, agg_cb, WOFF(Wm1,3), BOFF(bm1,3), xs_bc, NB, nullptr, FLAG_GELU);
            addJob(T, agg_bc, WOFF(Wm1,1), BOFF(bm1,1), xs_cc, NC, nullptr, FLAG_GELU);
            addJob(T, agg_cc, WOFF(Wm1,2), BOFF(bm1,2), xs_cb, NC, nullptr, FLAG_GELU);
            launch_tab(T);
        }
        // --- MLP2 ---
        {
            JobTab T = {};
            addJob(T, xs_bb, WOFF(Wm2,0), BOFF(bm2,0), agg_bb, NB, nullptr, 0);
            addJob(T, xs_bc, WOFF(Wm2,3), BOFF(bm2,3), agg_cb, NB, nullptr, 0);
            addJob(T, xs_cc, WOFF(Wm2,1), BOFF(bm2,1), agg_bc, NC, nullptr, 0);
            addJob(T, xs_cb, WOFF(Wm2,2), BOFF(bm2,2), agg_cc, NC, nullptr, 0);
            launch_tab(T);
        }
        // --- residual + gelu combine ---
        combine_kernel<<<(NBF+255)/256, 256>>>(xb, agg_bb, agg_cb, NBF);
        combine_kernel<<<(NCF+255)/256, 256>>>(xc, agg_bc, agg_cc, NCF);
        #undef WOFF
        #undef BOFF
    }

    float* out = (float*)d_out;
    cudaMemcpyAsync(out,       xb, sizeof(float)*(size_t)NBF, cudaMemcpyDeviceToDevice, 0);
    cudaMemcpyAsync(out + NBF, xc, sizeof(float)*(size_t)NCF, cudaMemcpyDeviceToDevice, 0);
}